// round 1
// baseline (speedup 1.0000x reference)
#include <cuda_runtime.h>
#include <cuda_bf16.h>

// Problem constants (fixed shapes for this problem)
#define NN 50000
#define EE 800000
#define DD 128
#define HH 32

// -------- scratch (no allocations allowed) --------
__device__ __align__(16) float g_y1[NN * HH];    // x @ W1_l^T
__device__ __align__(16) float g_z1[NN * HH];    // x @ W1_r^T
__device__ __align__(16) float g_agg[NN * HH];   // scatter-sum of y1
__device__ float g_deg[NN];
__device__ float g_sl[NN];                       // h @ W2_l^T
__device__ float g_sr[NN];                       // h @ W2_r^T
__device__ float g_agg2[NN];                     // scatter-sum of s_l
__device__ int   g_is64;                         // edge_index dtype flag

// -------- dtype detection: int64 edge_index has zero high words --------
__global__ void detect_kernel(const unsigned* __restrict__ ei_words) {
    __shared__ int flag;
    if (threadIdx.x == 0) flag = 1;
    __syncthreads();
    // check high word of first 256 would-be int64 values
    unsigned w = ei_words[2 * threadIdx.x + 1];
    if (w != 0u) flag = 0;
    __syncthreads();
    if (threadIdx.x == 0) g_is64 = flag;
}

__device__ __forceinline__ long long edge_at(const void* ei, long long pos, int is64) {
    if (is64) return ((const long long*)ei)[pos];
    return (long long)((const int*)ei)[pos];
}

// -------- zero accumulators --------
__global__ void zero_kernel(int n) {
    int total = n * HH + 2 * n;
    for (int i = blockIdx.x * blockDim.x + threadIdx.x; i < total;
         i += gridDim.x * blockDim.x) {
        if (i < n * HH)            g_agg[i] = 0.0f;
        else if (i < n * HH + n)   g_deg[i - n * HH] = 0.0f;
        else                       g_agg2[i - n * HH - n] = 0.0f;
    }
}

// -------- fused linear: y1 = x@W1_l^T, z1 = x@W1_r^T --------
// 32 nodes per block, 256 threads. smem: x tile + transposed combined W.
__global__ __launch_bounds__(256) void lin1_kernel(
    const float* __restrict__ x,
    const float* __restrict__ W1l,
    const float* __restrict__ W1r,
    int n)
{
    __shared__ float xs[32][DD];     // 16 KB
    __shared__ float wt[DD][64];     // 32 KB, wt[k][j] = W[j][k]
    int tid = threadIdx.x;
    int node0 = blockIdx.x * 32;

    // load combined transposed weights
    for (int idx = tid; idx < DD * 64; idx += 256) {
        int k = idx >> 6, j = idx & 63;
        wt[k][j] = (j < HH) ? W1l[j * DD + k] : W1r[(j - HH) * DD + k];
    }
    // load x tile (vectorized)
    int nvalid = n - node0; if (nvalid > 32) nvalid = 32;
    const float4* xg = (const float4*)(x + (size_t)node0 * DD);
    float4* xs4 = (float4*)&xs[0][0];
    for (int idx = tid; idx < 32 * (DD / 4); idx += 256) {
        int nn = idx / (DD / 4);
        xs4[idx] = (nn < nvalid) ? xg[idx] : make_float4(0.f, 0.f, 0.f, 0.f);
    }
    __syncthreads();

    int j  = tid & 63;    // output column (0..31 -> y1, 32..63 -> z1)
    int ng = tid >> 6;    // node group 0..3 (8 nodes each)
    float acc[8];
#pragma unroll
    for (int i = 0; i < 8; i++) acc[i] = 0.0f;

    for (int k = 0; k < DD; k += 4) {
        float w0 = wt[k][j], w1 = wt[k + 1][j], w2 = wt[k + 2][j], w3 = wt[k + 3][j];
#pragma unroll
        for (int i = 0; i < 8; i++) {
            float4 xv = *(const float4*)&xs[ng * 8 + i][k];
            acc[i] = fmaf(xv.x, w0, acc[i]);
            acc[i] = fmaf(xv.y, w1, acc[i]);
            acc[i] = fmaf(xv.z, w2, acc[i]);
            acc[i] = fmaf(xv.w, w3, acc[i]);
        }
    }

    float* outp = (j < HH) ? g_y1 : g_z1;
    int jj = j & 31;
#pragma unroll
    for (int i = 0; i < 8; i++) {
        int node = node0 + ng * 8 + i;
        if (node < n) outp[node * HH + jj] = acc[i];
    }
}

// -------- layer-1 edge scatter: agg[dst] += y1[src], deg[dst] += 1 --------
// 8 threads per edge, float4 vector atomics (sm_90+).
__global__ __launch_bounds__(256) void scatter1_kernel(const void* __restrict__ ei, long long E) {
    long long t = (long long)blockIdx.x * blockDim.x + threadIdx.x;
    long long e = t >> 3;
    int sub = (int)(t & 7);
    if (e >= E) return;
    int is64 = g_is64;
    long long src = edge_at(ei, e, is64);
    long long dst = edge_at(ei, E + e, is64);
    float4 v = *(const float4*)&g_y1[src * HH + sub * 4];
    atomicAdd((float4*)&g_agg[dst * HH + sub * 4], v);
    if (sub == 0) atomicAdd(&g_deg[dst], 1.0f);
}

// -------- layer-1 epilogue + layer-2 linear (warp per node) --------
__global__ __launch_bounds__(256) void epi_kernel(
    const float* __restrict__ b1,
    const float* __restrict__ W2l,
    const float* __restrict__ W2r,
    int n)
{
    int warp = (blockIdx.x * blockDim.x + threadIdx.x) >> 5;
    int lane = threadIdx.x & 31;
    if (warp >= n) return;
    float deg = g_deg[warp];
    float rdeg = 1.0f / fmaxf(deg, 1.0f);
    float hv = g_agg[warp * HH + lane] * rdeg + b1[lane] + g_z1[warp * HH + lane];
    hv = fmaxf(hv, 0.0f);  // relu
    float sl = hv * W2l[lane];
    float sr = hv * W2r[lane];
#pragma unroll
    for (int o = 16; o; o >>= 1) {
        sl += __shfl_xor_sync(0xFFFFFFFFu, sl, o);
        sr += __shfl_xor_sync(0xFFFFFFFFu, sr, o);
    }
    if (lane == 0) { g_sl[warp] = sl; g_sr[warp] = sr; }
}

// -------- layer-2 edge scatter: agg2[dst] += s_l[src] --------
__global__ __launch_bounds__(256) void scatter2_kernel(const void* __restrict__ ei, long long E) {
    long long e = (long long)blockIdx.x * blockDim.x + threadIdx.x;
    if (e >= E) return;
    int is64 = g_is64;
    long long src = edge_at(ei, e, is64);
    long long dst = edge_at(ei, E + e, is64);
    atomicAdd(&g_agg2[dst], g_sl[src]);
}

// -------- final: sigmoid(agg2/deg + b2 + s_r) --------
__global__ __launch_bounds__(256) void final_kernel(const float* __restrict__ b2,
                                                    float* __restrict__ out, int n) {
    int i = blockIdx.x * blockDim.x + threadIdx.x;
    if (i >= n) return;
    float rdeg = 1.0f / fmaxf(g_deg[i], 1.0f);
    float v = g_agg2[i] * rdeg + b2[0] + g_sr[i];
    out[i] = 1.0f / (1.0f + expf(-v));
}

extern "C" void kernel_launch(void* const* d_in, const int* in_sizes, int n_in,
                              void* d_out, int out_size) {
    const float* x   = (const float*)d_in[0];
    const void*  ei  = d_in[1];
    const float* W1l = (const float*)d_in[2];
    const float* b1  = (const float*)d_in[3];
    const float* W1r = (const float*)d_in[4];
    const float* W2l = (const float*)d_in[5];
    const float* b2  = (const float*)d_in[6];
    const float* W2r = (const float*)d_in[7];
    float* out = (float*)d_out;

    int n = in_sizes[0] / DD;            // 50000
    long long E = in_sizes[1] / 2;       // 800000 (element count same for i32/i64)

    detect_kernel<<<1, 256>>>((const unsigned*)ei);
    {
        int total = n * HH + 2 * n;
        zero_kernel<<<(total + 255) / 256, 256>>>(n);
    }
    lin1_kernel<<<(n + 31) / 32, 256>>>(x, W1l, W1r, n);
    {
        long long threads = E * 8;
        scatter1_kernel<<<(unsigned)((threads + 255) / 256), 256>>>(ei, E);
    }
    epi_kernel<<<(n * 32 + 255) / 256, 256>>>(b1, W2l, W2r, n);
    scatter2_kernel<<<(unsigned)((E + 255) / 256), 256>>>(ei, E);
    final_kernel<<<(n + 255) / 256, 256>>>(b2, out, n);
}